// round 3
// baseline (speedup 1.0000x reference)
#include <cuda_runtime.h>
#include <cuda_bf16.h>

// ---------------------------------------------------------------------------
// GNN15: two GAT branches (int: 400K edges deg~4, nh: 1.6M edges deg~16)
// over 100K nodes, HEADS=3, FILT=16, then attention pooling to a scalar.
//
// R3: on-the-fly CSR (counting sort by dst) so the 48-float scatter happens
// once per (quad,row) instead of once per edge. Register accumulation in the
// consume kernel; red.v4 only at dst-change boundaries.
// ---------------------------------------------------------------------------

#define NN      100000
#define E_INT   400000
#define E_NH    1600000
#define VF      11
#define HEADS   3
#define HF      48      // HEADS*FILT
#define HSTRIDE 64      // h row: 48 h + (es0,es1,es2,0) @48 + pad -> 256B
#define XDIM    96      // 2*HF
#define NBLK    98      // scan blocks per branch (98*1024 >= 100000)

// ---------------- scratch (static device globals; no allocation) -----------
__device__ __align__(16) float g_h0[NN * HSTRIDE];   // h row + embedded es
__device__ __align__(16) float g_h1[NN * HSTRIDE];
__device__ __align__(16) float4 g_ed4_0[NN];
__device__ __align__(16) float4 g_ed4_1[NN];
__device__ __align__(16) float4 g_den4_0[NN];
__device__ __align__(16) float4 g_den4_1[NN];
__device__ __align__(16) float g_out0[NN * HF];      // UNNORMALIZED sums
__device__ __align__(16) float g_out1[NN * HF];
__device__ int  g_cnt0[NN];
__device__ int  g_cnt1[NN];
__device__ int  g_cur0[NN];                          // running cursors (scan result)
__device__ int  g_cur1[NN];
__device__ int  g_part[2 * NBLK];                    // scan partials
__device__ __align__(8) int2 g_pe0[E_INT];           // dst-sorted (src,dst)
__device__ __align__(8) int2 g_pe1[E_NH];
__device__ float g_acc[8];                           // num[3], den[3]
__device__ int   g_is64[2];

// ---------------- init: zero counters + detect edge dtype ------------------
// jax "int64" edges are int32 unless x64 is enabled. Values < 1e5 << 2^31,
// so if truly int64 every odd int32 word is 0. Check 16 of them.
__global__ void init_kernel(const void* e0, const void* e1) {
    int i = blockIdx.x * blockDim.x + threadIdx.x;
    int stride = gridDim.x * blockDim.x;
    for (int k = i; k < NN; k += stride) { g_cnt0[k] = 0; g_cnt1[k] = 0; }
    if (i == 0) {
        const int* a = (const int*)e0;
        const int* b = (const int*)e1;
        int is64a = 1, is64b = 1;
        #pragma unroll
        for (int t = 0; t < 16; t++) {
            if (a[2 * t + 1] != 0) is64a = 0;
            if (b[2 * t + 1] != 0) is64b = 0;
        }
        g_is64[0] = is64a;
        g_is64[1] = is64b;
        #pragma unroll
        for (int t = 0; t < 8; t++) g_acc[t] = 0.0f;
    }
}

// ---------------- node transform + zero accumulators -----------------------
__global__ void node_kernel(const float* __restrict__ feats,
                            const float* __restrict__ W0,
                            const float* __restrict__ as0, const float* __restrict__ ad0,
                            const float* __restrict__ W1,
                            const float* __restrict__ as1, const float* __restrict__ ad1) {
    __shared__ float sW[2][VF * HF];
    __shared__ float sAs[2][HF];
    __shared__ float sAd[2][HF];
    int tid = threadIdx.x;
    for (int i = tid; i < VF * HF; i += blockDim.x) { sW[0][i] = W0[i]; sW[1][i] = W1[i]; }
    for (int i = tid; i < HF; i += blockDim.x) {
        sAs[0][i] = as0[i]; sAd[0][i] = ad0[i];
        sAs[1][i] = as1[i]; sAd[1][i] = ad1[i];
    }
    __syncthreads();

    int n = blockIdx.x * blockDim.x + tid;
    if (n >= NN) return;

    float x[VF];
    #pragma unroll
    for (int k = 0; k < VF; k++) x[k] = feats[(size_t)n * VF + k];

    float4 z4 = make_float4(0.f, 0.f, 0.f, 0.f);
    #pragma unroll
    for (int b = 0; b < 2; b++) {
        float* hout = (b == 0 ? g_h0 : g_h1) + (size_t)n * HSTRIDE;
        float es[HEADS] = {0.f, 0.f, 0.f};
        float ed[HEADS] = {0.f, 0.f, 0.f};
        #pragma unroll
        for (int j = 0; j < HF; j++) {
            float s = 0.f;
            #pragma unroll
            for (int k = 0; k < VF; k++) s += x[k] * sW[b][k * HF + j];
            hout[j] = s;
            int hh = j >> 4;
            es[hh] += s * sAs[b][j];
            ed[hh] += s * sAd[b][j];
        }
        ((float4*)hout)[12] = make_float4(es[0], es[1], es[2], 0.f);  // es @ float 48
        (b == 0 ? g_ed4_0 : g_ed4_1)[n] = make_float4(ed[0], ed[1], ed[2], 0.f);
        (b == 0 ? g_den4_0 : g_den4_1)[n] = z4;
        float4* o = (float4*)((b == 0 ? g_out0 : g_out1) + (size_t)n * HF);
        #pragma unroll
        for (int j = 0; j < HF / 4; j++) o[j] = z4;
    }
}

// ---------------- CSR build: histogram -------------------------------------
__global__ void hist_kernel(const void* __restrict__ edges, int E, int which,
                            int* __restrict__ cnt) {
    int e = blockIdx.x * blockDim.x + threadIdx.x;
    if (e >= E) return;
    int d;
    if (g_is64[which]) d = (int)((const long long*)edges)[E + e];
    else               d = ((const int*)edges)[E + e];
    atomicAdd(&cnt[d], 1);
}

// ---------------- scan phase A: per-block partial sums ---------------------
__global__ void scan_partial_kernel() {
    int b = blockIdx.x;
    const int* cnt = (b < NBLK) ? g_cnt0 : g_cnt1;
    int bb = (b < NBLK) ? b : b - NBLK;
    int t = threadIdx.x;
    int base = bb * 1024 + t * 4;
    int s = 0;
    #pragma unroll
    for (int i = 0; i < 4; i++) if (base + i < NN) s += cnt[base + i];
    #pragma unroll
    for (int off = 16; off > 0; off >>= 1) s += __shfl_down_sync(0xFFFFFFFFu, s, off);
    __shared__ int ws[8];
    if ((t & 31) == 0) ws[t >> 5] = s;
    __syncthreads();
    if (t < 8) {
        int v = ws[t];
        #pragma unroll
        for (int off = 4; off > 0; off >>= 1) v += __shfl_down_sync(0xFFu, v, off);
        if (t == 0) g_part[b] = v;
    }
}

// ---------------- scan phase B: scan the 196 partials (reset at branch) ----
__global__ void scan_mid_kernel() {
    int t = threadIdx.x;
    int v = (t < 2 * NBLK) ? g_part[t] : 0;
    int x = v;
    #pragma unroll
    for (int off = 1; off < 32; off <<= 1) {
        int y = __shfl_up_sync(0xFFFFFFFFu, x, off);
        if ((t & 31) >= off) x += y;
    }
    __shared__ int ws[8];
    __shared__ int wbase[8];
    __shared__ int seg0;
    int warp = t >> 5;
    if ((t & 31) == 31) ws[warp] = x;
    __syncthreads();
    if (t < 8) {
        int wv = ws[t];
        int wx = wv;
        #pragma unroll
        for (int off = 1; off < 8; off <<= 1) {
            int y = __shfl_up_sync(0xFFu, wx, off);
            if (t >= off) wx += y;
        }
        wbase[t] = wx - wv;
    }
    __syncthreads();
    int incl = x + wbase[warp];
    int excl = incl - v;
    if (t == NBLK - 1) seg0 = incl;     // total of branch-0 counts
    __syncthreads();
    if (t < 2 * NBLK) g_part[t] = (t < NBLK) ? excl : (excl - seg0);
}

// ---------------- scan phase C: full exclusive scan -> cursors -------------
__global__ void scan_final_kernel() {
    int b = blockIdx.x;
    const int* cnt = (b < NBLK) ? g_cnt0 : g_cnt1;
    int* cur       = (b < NBLK) ? g_cur0 : g_cur1;
    int bb = (b < NBLK) ? b : b - NBLK;
    int t = threadIdx.x;
    int base = bb * 1024 + t * 4;
    int v[4]; int ts = 0;
    #pragma unroll
    for (int i = 0; i < 4; i++) {
        v[i] = (base + i < NN) ? cnt[base + i] : 0;
        ts += v[i];
    }
    int x = ts;
    #pragma unroll
    for (int off = 1; off < 32; off <<= 1) {
        int y = __shfl_up_sync(0xFFFFFFFFu, x, off);
        if ((t & 31) >= off) x += y;
    }
    __shared__ int ws[8];
    __shared__ int wbase[8];
    int warp = t >> 5;
    if ((t & 31) == 31) ws[warp] = x;
    __syncthreads();
    if (t < 8) {
        int wv = ws[t];
        int wx = wv;
        #pragma unroll
        for (int off = 1; off < 8; off <<= 1) {
            int y = __shfl_up_sync(0xFFu, wx, off);
            if (t >= off) wx += y;
        }
        wbase[t] = wx - wv;
    }
    __syncthreads();
    int run = g_part[b] + wbase[warp] + (x - ts);
    #pragma unroll
    for (int i = 0; i < 4; i++) {
        if (base + i < NN) cur[base + i] = run;
        run += v[i];
    }
}

// ---------------- permute edges into dst-grouped order ---------------------
__global__ void permute_kernel(const void* __restrict__ edges, int E, int which,
                               int* __restrict__ cur, int2* __restrict__ pe) {
    int e = blockIdx.x * blockDim.x + threadIdx.x;
    if (e >= E) return;
    int s, d;
    if (g_is64[which]) {
        const long long* E64 = (const long long*)edges;
        s = (int)E64[e]; d = (int)E64[E + e];
    } else {
        const int* E32 = (const int*)edges;
        s = E32[e]; d = E32[E + e];
    }
    int pos = atomicAdd(&cur[d], 1);
    pe[pos] = make_int2(s, d);
}

// ---------------- consume: quad walks a contiguous dst-sorted range --------
// Accumulate sum(p * h[src]) + sum(p) in registers; red.v4 only on dst change.
__device__ __forceinline__ void quad_flush(float* __restrict__ out,
                                           float4* __restrict__ den4,
                                           int d, int lane,
                                           float4 a0, float4 a1, float4 a2,
                                           float d0, float d1, float d2) {
    float* ob = out + (size_t)d * HF + lane * 4;
    asm volatile("red.global.add.v4.f32 [%0], {%1,%2,%3,%4};"
                 :: "l"(ob), "f"(a0.x), "f"(a0.y), "f"(a0.z), "f"(a0.w) : "memory");
    asm volatile("red.global.add.v4.f32 [%0], {%1,%2,%3,%4};"
                 :: "l"(ob + 16), "f"(a1.x), "f"(a1.y), "f"(a1.z), "f"(a1.w) : "memory");
    asm volatile("red.global.add.v4.f32 [%0], {%1,%2,%3,%4};"
                 :: "l"(ob + 32), "f"(a2.x), "f"(a2.y), "f"(a2.z), "f"(a2.w) : "memory");
    if (lane == 0) {
        float* da = (float*)&den4[d];
        asm volatile("red.global.add.v4.f32 [%0], {%1,%2,%3,%4};"
                     :: "l"(da), "f"(d0), "f"(d1), "f"(d2), "f"(0.f) : "memory");
    }
}

__global__ void __launch_bounds__(256) consume_kernel(
        const int2* __restrict__ pe, int E,
        const float* __restrict__ h,
        const float4* __restrict__ ed4,
        float4* __restrict__ den4, float* __restrict__ out) {
    int t = blockIdx.x * blockDim.x + threadIdx.x;
    int q = t >> 2, lane = t & 3;
    int nq = (gridDim.x * blockDim.x) >> 2;
    int a   = (int)((long long)q * E / nq);
    int bnd = (int)((long long)(q + 1) * E / nq);

    int curd = -1;
    float4 acc0 = {0,0,0,0}, acc1 = {0,0,0,0}, acc2 = {0,0,0,0};
    float d0 = 0.f, d1 = 0.f, d2 = 0.f;
    float4 ed = {0,0,0,0};

    for (int e = a; e < bnd; e++) {
        int2 sd = pe[e];
        if (sd.y != curd) {
            if (curd >= 0)
                quad_flush(out, den4, curd, lane, acc0, acc1, acc2, d0, d1, d2);
            curd = sd.y;
            ed = ed4[curd];
            acc0 = acc1 = acc2 = make_float4(0.f, 0.f, 0.f, 0.f);
            d0 = d1 = d2 = 0.f;
        }
        const float4* hr = (const float4*)(h + (size_t)sd.x * HSTRIDE);
        float4 es = hr[12];                     // embedded src scores
        float v0 = es.x + ed.x, v1 = es.y + ed.y, v2 = es.z + ed.z;
        v0 = v0 > 0.f ? v0 : 0.2f * v0;         // leaky_relu(0.2)
        v1 = v1 > 0.f ? v1 : 0.2f * v1;
        v2 = v2 > 0.f ? v2 : 0.2f * v2;
        float p0 = __expf(v0);                  // no max-shift needed (|v| small)
        float p1 = __expf(v1);
        float p2 = __expf(v2);
        d0 += p0; d1 += p1; d2 += p2;
        float4 h0v = hr[lane];
        float4 h1v = hr[4 + lane];
        float4 h2v = hr[8 + lane];
        acc0.x += p0 * h0v.x; acc0.y += p0 * h0v.y; acc0.z += p0 * h0v.z; acc0.w += p0 * h0v.w;
        acc1.x += p1 * h1v.x; acc1.y += p1 * h1v.y; acc1.z += p1 * h1v.z; acc1.w += p1 * h1v.w;
        acc2.x += p2 * h2v.x; acc2.y += p2 * h2v.y; acc2.z += p2 * h2v.z; acc2.w += p2 * h2v.w;
    }
    if (curd >= 0)
        quad_flush(out, den4, curd, lane, acc0, acc1, acc2, d0, d1, d2);
}

// ---------------- pooling: normalize + fused tanh-attention reduction ------
__global__ void pool_kernel(const float* __restrict__ attw,
                            const float* __restrict__ dw) {
    __shared__ float sA[XDIM * HEADS];   // attw: [96,3] row-major
    __shared__ float sD[XDIM * HEADS];   // dense_w: [288] = [3][96] h-major
    int tid = threadIdx.x;
    for (int i = tid; i < XDIM * HEADS; i += blockDim.x) { sA[i] = attw[i]; sD[i] = dw[i]; }
    __syncthreads();

    int n = blockIdx.x * blockDim.x + tid;
    float sh[HEADS] = {0.f, 0.f, 0.f};
    float dh[HEADS] = {0.f, 0.f, 0.f};
    if (n < NN) {
        float4 dn0 = g_den4_0[n];
        float4 dn1 = g_den4_1[n];
        float inv0[HEADS] = {1.f / (dn0.x + 1e-16f), 1.f / (dn0.y + 1e-16f), 1.f / (dn0.z + 1e-16f)};
        float inv1[HEADS] = {1.f / (dn1.x + 1e-16f), 1.f / (dn1.y + 1e-16f), 1.f / (dn1.z + 1e-16f)};
        const float4* x0 = (const float4*)(g_out0 + (size_t)n * HF);
        const float4* x1 = (const float4*)(g_out1 + (size_t)n * HF);
        #pragma unroll
        for (int j = 0; j < HF / 4; j++) {
            float4 v0 = x0[j];
            float4 v1 = x1[j];
            int hh = j >> 2;
            float q0[4] = {v0.x * inv0[hh], v0.y * inv0[hh], v0.z * inv0[hh], v0.w * inv0[hh]};
            float q1[4] = {v1.x * inv1[hh], v1.y * inv1[hh], v1.z * inv1[hh], v1.w * inv1[hh]};
            #pragma unroll
            for (int c = 0; c < 4; c++) {
                int dA = j * 4 + c;
                int dB = dA + HF;
                #pragma unroll
                for (int h = 0; h < HEADS; h++) {
                    sh[h] += q0[c] * sA[dA * HEADS + h] + q1[c] * sA[dB * HEADS + h];
                    dh[h] += q0[c] * sD[h * XDIM + dA] + q1[c] * sD[h * XDIM + dB];
                }
            }
        }
    }
    float num[HEADS], den[HEADS];
    #pragma unroll
    for (int h = 0; h < HEADS; h++) {
        float w = (n < NN) ? __expf(tanhf(sh[h])) : 0.f;
        num[h] = w * dh[h];
        den[h] = w;
    }
    #pragma unroll
    for (int off = 16; off > 0; off >>= 1) {
        #pragma unroll
        for (int h = 0; h < HEADS; h++) {
            num[h] += __shfl_down_sync(0xFFFFFFFFu, num[h], off);
            den[h] += __shfl_down_sync(0xFFFFFFFFu, den[h], off);
        }
    }
    if ((tid & 31) == 0) {
        #pragma unroll
        for (int h = 0; h < HEADS; h++) {
            atomicAdd(&g_acc[h], num[h]);
            atomicAdd(&g_acc[HEADS + h], den[h]);
        }
    }
}

__global__ void finalize_kernel(const float* __restrict__ bias, float* __restrict__ out) {
    float r = 0.f;
    #pragma unroll
    for (int h = 0; h < HEADS; h++) r += g_acc[h] / g_acc[HEADS + h];
    out[0] = r + bias[0];
}

// ---------------------------------------------------------------------------
extern "C" void kernel_launch(void* const* d_in, const int* in_sizes, int n_in,
                              void* d_out, int out_size) {
    const float* node_feats = (const float*)d_in[0];
    const float* W_int   = (const float*)d_in[1];
    const float* asrc_i  = (const float*)d_in[2];
    const float* adst_i  = (const float*)d_in[3];
    const float* W_nh    = (const float*)d_in[4];
    const float* asrc_n  = (const float*)d_in[5];
    const float* adst_n  = (const float*)d_in[6];
    const float* att_w   = (const float*)d_in[7];
    const float* dense_w = (const float*)d_in[8];
    const float* dense_b = (const float*)d_in[9];
    const void*  edge_i  = d_in[10];
    const void*  edge_n  = d_in[11];
    float* out = (float*)d_out;

    int* pcnt0; cudaGetSymbolAddress((void**)&pcnt0, g_cnt0);
    int* pcnt1; cudaGetSymbolAddress((void**)&pcnt1, g_cnt1);
    int* pcur0; cudaGetSymbolAddress((void**)&pcur0, g_cur0);
    int* pcur1; cudaGetSymbolAddress((void**)&pcur1, g_cur1);
    int2* ppe0; cudaGetSymbolAddress((void**)&ppe0, g_pe0);
    int2* ppe1; cudaGetSymbolAddress((void**)&ppe1, g_pe1);
    float* ph0;   cudaGetSymbolAddress((void**)&ph0, g_h0);
    float* ph1;   cudaGetSymbolAddress((void**)&ph1, g_h1);
    float4* ped0; cudaGetSymbolAddress((void**)&ped0, g_ed4_0);
    float4* ped1; cudaGetSymbolAddress((void**)&ped1, g_ed4_1);
    float4* pden0; cudaGetSymbolAddress((void**)&pden0, g_den4_0);
    float4* pden1; cudaGetSymbolAddress((void**)&pden1, g_den4_1);
    float* pout0; cudaGetSymbolAddress((void**)&pout0, g_out0);
    float* pout1; cudaGetSymbolAddress((void**)&pout1, g_out1);

    init_kernel<<<100, 256>>>(edge_i, edge_n);
    node_kernel<<<(NN + 255) / 256, 256>>>(node_feats, W_int, asrc_i, adst_i,
                                           W_nh, asrc_n, adst_n);

    hist_kernel<<<(E_INT + 255) / 256, 256>>>(edge_i, E_INT, 0, pcnt0);
    hist_kernel<<<(E_NH + 255) / 256, 256>>>(edge_n, E_NH, 1, pcnt1);

    scan_partial_kernel<<<2 * NBLK, 256>>>();
    scan_mid_kernel<<<1, 256>>>();
    scan_final_kernel<<<2 * NBLK, 256>>>();

    permute_kernel<<<(E_INT + 255) / 256, 256>>>(edge_i, E_INT, 0, pcur0, ppe0);
    permute_kernel<<<(E_NH + 255) / 256, 256>>>(edge_n, E_NH, 1, pcur1, ppe1);

    consume_kernel<<<148, 256>>>(ppe0, E_INT, ph0, ped0, pden0, pout0);
    consume_kernel<<<296, 256>>>(ppe1, E_NH, ph1, ped1, pden1, pout1);

    pool_kernel<<<(NN + 255) / 256, 256>>>(att_w, dense_w);
    finalize_kernel<<<1, 1>>>(dense_b, out);
}

// round 4
// speedup vs baseline: 1.3089x; 1.3089x over previous
#include <cuda_runtime.h>
#include <cuda_bf16.h>

// ---------------------------------------------------------------------------
// GNN15: two GAT branches (int: 400K edges, nh: 1.6M edges) over 100K nodes,
// HEADS=3, FILT=16, then attention pooling to a scalar.
//
// R4: back to the R2 fused single edge pass (R3 CSR consume was latency-bound).
// Improvements: 8 threads/edge octets, h and out rows padded to 256B and
// 128B-aligned so gather = 2 line-touches and scatter = 2 line-touches/edge.
//   out[d] = (sum_e p_e * h[src_e]) / (den[d] + eps)   (normalize in pooling)
// ---------------------------------------------------------------------------

#define NN      100000
#define E_INT   400000
#define E_NH    1600000
#define VF      11
#define HEADS   3
#define HF      48       // HEADS*FILT
#define RSTRIDE 64       // padded row stride (floats) = 256B, 128B-aligned
#define XDIM    96       // 2*HF

// ---------------- scratch (static device globals; no allocation) -----------
__device__ __align__(256) float g_h0[NN * RSTRIDE];
__device__ __align__(256) float g_h1[NN * RSTRIDE];
__device__ __align__(16) float4 g_es4_0[NN];
__device__ __align__(16) float4 g_ed4_0[NN];
__device__ __align__(16) float4 g_es4_1[NN];
__device__ __align__(16) float4 g_ed4_1[NN];
__device__ __align__(16) float4 g_den4_0[NN];
__device__ __align__(16) float4 g_den4_1[NN];
__device__ __align__(256) float g_out0[NN * RSTRIDE];   // UNNORMALIZED sums
__device__ __align__(256) float g_out1[NN * RSTRIDE];
__device__ float g_acc[8];                              // num[3], den[3]
__device__ int   g_is64[2];

// ---------------- init: detect edge dtype + zero acc -----------------------
// jax "int64" edges are int32 unless x64 is enabled. Values < 1e5 << 2^31,
// so if truly int64 every odd int32 word is 0. Check 16 of them.
__global__ void init_kernel(const void* e0, const void* e1) {
    if (threadIdx.x == 0) {
        const int* a = (const int*)e0;
        const int* b = (const int*)e1;
        int is64a = 1, is64b = 1;
        #pragma unroll
        for (int t = 0; t < 16; t++) {
            if (a[2 * t + 1] != 0) is64a = 0;
            if (b[2 * t + 1] != 0) is64b = 0;
        }
        g_is64[0] = is64a;
        g_is64[1] = is64b;
        #pragma unroll
        for (int t = 0; t < 8; t++) g_acc[t] = 0.0f;
    }
}

// ---------------- node transform + zero accumulators -----------------------
__global__ void node_kernel(const float* __restrict__ feats,
                            const float* __restrict__ W0,
                            const float* __restrict__ as0, const float* __restrict__ ad0,
                            const float* __restrict__ W1,
                            const float* __restrict__ as1, const float* __restrict__ ad1) {
    __shared__ float sW[2][VF * HF];
    __shared__ float sAs[2][HF];
    __shared__ float sAd[2][HF];
    int tid = threadIdx.x;
    for (int i = tid; i < VF * HF; i += blockDim.x) { sW[0][i] = W0[i]; sW[1][i] = W1[i]; }
    for (int i = tid; i < HF; i += blockDim.x) {
        sAs[0][i] = as0[i]; sAd[0][i] = ad0[i];
        sAs[1][i] = as1[i]; sAd[1][i] = ad1[i];
    }
    __syncthreads();

    int n = blockIdx.x * blockDim.x + tid;
    if (n >= NN) return;

    float x[VF];
    #pragma unroll
    for (int k = 0; k < VF; k++) x[k] = feats[(size_t)n * VF + k];

    float4 z4 = make_float4(0.f, 0.f, 0.f, 0.f);
    #pragma unroll
    for (int b = 0; b < 2; b++) {
        float* hout = (b == 0 ? g_h0 : g_h1) + (size_t)n * RSTRIDE;
        float es[HEADS] = {0.f, 0.f, 0.f};
        float ed[HEADS] = {0.f, 0.f, 0.f};
        #pragma unroll
        for (int j = 0; j < HF; j++) {
            float s = 0.f;
            #pragma unroll
            for (int k = 0; k < VF; k++) s += x[k] * sW[b][k * HF + j];
            hout[j] = s;
            int hh = j >> 4;
            es[hh] += s * sAs[b][j];
            ed[hh] += s * sAd[b][j];
        }
        (b == 0 ? g_es4_0 : g_es4_1)[n] = make_float4(es[0], es[1], es[2], 0.f);
        (b == 0 ? g_ed4_0 : g_ed4_1)[n] = make_float4(ed[0], ed[1], ed[2], 0.f);
        (b == 0 ? g_den4_0 : g_den4_1)[n] = z4;
        float4* o = (float4*)((b == 0 ? g_out0 : g_out1) + (size_t)n * RSTRIDE);
        #pragma unroll
        for (int j = 0; j < HF / 4; j++) o[j] = z4;
    }
}

// ---------------- fused edge pass: den += p ; out[dst] += p * h[src] -------
// 8 threads per edge. Gather = 2 line-touches (128B + 64B of a 256B-aligned
// row); scatter = 2 red.v4 line-touches. All lanes compute p (MUFU is
// per-warp-instruction cost, negligible); lane 0 reds the denominator.
__global__ void __launch_bounds__(256) edge_fused(
        const void* __restrict__ edges, int E, int which,
        const float* __restrict__ h,
        const float4* __restrict__ es4, const float4* __restrict__ ed4,
        float4* __restrict__ den4, float* __restrict__ out) {
    int t = blockIdx.x * blockDim.x + threadIdx.x;
    int e = t >> 3;
    int sub = t & 7;
    if (e >= E) return;
    int s, d;
    if (g_is64[which]) {
        const long long* E64 = (const long long*)edges;
        s = (int)E64[e]; d = (int)E64[E + e];
    } else {
        const int* E32 = (const int*)edges;
        s = E32[e]; d = E32[E + e];
    }
    float4 a = es4[s];
    float4 b = ed4[d];
    float v0 = a.x + b.x, v1 = a.y + b.y, v2 = a.z + b.z;
    v0 = v0 > 0.f ? v0 : 0.2f * v0;           // leaky_relu(0.2)
    v1 = v1 > 0.f ? v1 : 0.2f * v1;
    v2 = v2 > 0.f ? v2 : 0.2f * v2;
    float p0 = __expf(v0);                    // no max-shift needed (|v| small)
    float p1 = __expf(v1);
    float p2 = __expf(v2);

    if (sub == 0) {
        float* daddr = (float*)&den4[d];
        asm volatile("red.global.add.v4.f32 [%0], {%1,%2,%3,%4};"
                     :: "l"(daddr), "f"(p0), "f"(p1), "f"(p2), "f"(0.f)
                     : "memory");
    }

    const float4* hr = (const float4*)(h + (size_t)s * RSTRIDE);
    float* ob = out + (size_t)d * RSTRIDE;

    // first 128B: float4 slots 0..7 (heads 0 and 1)
    float4 hv = hr[sub];
    float pa = (sub < 4) ? p0 : p1;
    hv.x *= pa; hv.y *= pa; hv.z *= pa; hv.w *= pa;
    asm volatile("red.global.add.v4.f32 [%0], {%1,%2,%3,%4};"
                 :: "l"(ob + sub * 4), "f"(hv.x), "f"(hv.y), "f"(hv.z), "f"(hv.w)
                 : "memory");

    // next 64B: float4 slots 8..11 (head 2), lanes 0-3 only
    if (sub < 4) {
        float4 hw = hr[8 + sub];
        hw.x *= p2; hw.y *= p2; hw.z *= p2; hw.w *= p2;
        asm volatile("red.global.add.v4.f32 [%0], {%1,%2,%3,%4};"
                     :: "l"(ob + 32 + sub * 4), "f"(hw.x), "f"(hw.y), "f"(hw.z), "f"(hw.w)
                     : "memory");
    }
}

// ---------------- pooling: normalize + fused tanh-attention reduction ------
// x_n[d] = out_raw[n][d] / (den[n][head(d)] + 1e-16)
// out = sum_h ( sum_n e^{tanh(x_n . attw_h)} * (x_n . dw_h) )
//             / ( sum_n e^{tanh(x_n . attw_h)} )  + b
__global__ void pool_kernel(const float* __restrict__ attw,
                            const float* __restrict__ dw) {
    __shared__ float sA[XDIM * HEADS];   // attw: [96,3] row-major
    __shared__ float sD[XDIM * HEADS];   // dense_w: [288] = [3][96] h-major
    int tid = threadIdx.x;
    for (int i = tid; i < XDIM * HEADS; i += blockDim.x) { sA[i] = attw[i]; sD[i] = dw[i]; }
    __syncthreads();

    int n = blockIdx.x * blockDim.x + tid;
    float sh[HEADS] = {0.f, 0.f, 0.f};
    float dh[HEADS] = {0.f, 0.f, 0.f};
    if (n < NN) {
        float4 dn0 = g_den4_0[n];
        float4 dn1 = g_den4_1[n];
        float inv0[HEADS] = {1.f / (dn0.x + 1e-16f), 1.f / (dn0.y + 1e-16f), 1.f / (dn0.z + 1e-16f)};
        float inv1[HEADS] = {1.f / (dn1.x + 1e-16f), 1.f / (dn1.y + 1e-16f), 1.f / (dn1.z + 1e-16f)};
        const float4* x0 = (const float4*)(g_out0 + (size_t)n * RSTRIDE);
        const float4* x1 = (const float4*)(g_out1 + (size_t)n * RSTRIDE);
        #pragma unroll
        for (int j = 0; j < HF / 4; j++) {
            float4 v0 = x0[j];
            float4 v1 = x1[j];
            int hh = j >> 2;
            float q0[4] = {v0.x * inv0[hh], v0.y * inv0[hh], v0.z * inv0[hh], v0.w * inv0[hh]};
            float q1[4] = {v1.x * inv1[hh], v1.y * inv1[hh], v1.z * inv1[hh], v1.w * inv1[hh]};
            #pragma unroll
            for (int c = 0; c < 4; c++) {
                int dA = j * 4 + c;
                int dB = dA + HF;
                #pragma unroll
                for (int h = 0; h < HEADS; h++) {
                    sh[h] += q0[c] * sA[dA * HEADS + h] + q1[c] * sA[dB * HEADS + h];
                    dh[h] += q0[c] * sD[h * XDIM + dA] + q1[c] * sD[h * XDIM + dB];
                }
            }
        }
    }
    float num[HEADS], den[HEADS];
    #pragma unroll
    for (int h = 0; h < HEADS; h++) {
        float w = (n < NN) ? __expf(tanhf(sh[h])) : 0.f;
        num[h] = w * dh[h];
        den[h] = w;
    }
    #pragma unroll
    for (int off = 16; off > 0; off >>= 1) {
        #pragma unroll
        for (int h = 0; h < HEADS; h++) {
            num[h] += __shfl_down_sync(0xFFFFFFFFu, num[h], off);
            den[h] += __shfl_down_sync(0xFFFFFFFFu, den[h], off);
        }
    }
    if ((tid & 31) == 0) {
        #pragma unroll
        for (int h = 0; h < HEADS; h++) {
            atomicAdd(&g_acc[h], num[h]);
            atomicAdd(&g_acc[HEADS + h], den[h]);
        }
    }
}

__global__ void finalize_kernel(const float* __restrict__ bias, float* __restrict__ out) {
    float r = 0.f;
    #pragma unroll
    for (int h = 0; h < HEADS; h++) r += g_acc[h] / g_acc[HEADS + h];
    out[0] = r + bias[0];
}

// ---------------------------------------------------------------------------
extern "C" void kernel_launch(void* const* d_in, const int* in_sizes, int n_in,
                              void* d_out, int out_size) {
    const float* node_feats = (const float*)d_in[0];
    const float* W_int   = (const float*)d_in[1];
    const float* asrc_i  = (const float*)d_in[2];
    const float* adst_i  = (const float*)d_in[3];
    const float* W_nh    = (const float*)d_in[4];
    const float* asrc_n  = (const float*)d_in[5];
    const float* adst_n  = (const float*)d_in[6];
    const float* att_w   = (const float*)d_in[7];
    const float* dense_w = (const float*)d_in[8];
    const float* dense_b = (const float*)d_in[9];
    const void*  edge_i  = d_in[10];
    const void*  edge_n  = d_in[11];
    float* out = (float*)d_out;

    float* ph0;   cudaGetSymbolAddress((void**)&ph0, g_h0);
    float* ph1;   cudaGetSymbolAddress((void**)&ph1, g_h1);
    float4* pes0; cudaGetSymbolAddress((void**)&pes0, g_es4_0);
    float4* ped0; cudaGetSymbolAddress((void**)&ped0, g_ed4_0);
    float4* pes1; cudaGetSymbolAddress((void**)&pes1, g_es4_1);
    float4* ped1; cudaGetSymbolAddress((void**)&ped1, g_ed4_1);
    float4* pden0; cudaGetSymbolAddress((void**)&pden0, g_den4_0);
    float4* pden1; cudaGetSymbolAddress((void**)&pden1, g_den4_1);
    float* pout0; cudaGetSymbolAddress((void**)&pout0, g_out0);
    float* pout1; cudaGetSymbolAddress((void**)&pout1, g_out1);

    init_kernel<<<1, 32>>>(edge_i, edge_n);
    node_kernel<<<(NN + 255) / 256, 256>>>(node_feats, W_int, asrc_i, adst_i,
                                           W_nh, asrc_n, adst_n);

    edge_fused<<<(8 * E_INT + 255) / 256, 256>>>(edge_i, E_INT, 0, ph0, pes0, ped0, pden0, pout0);
    edge_fused<<<(8 * E_NH + 255) / 256, 256>>>(edge_n, E_NH, 1, ph1, pes1, ped1, pden1, pout1);

    pool_kernel<<<(NN + 255) / 256, 256>>>(att_w, dense_w);
    finalize_kernel<<<1, 1>>>(dense_b, out);
}

// round 5
// speedup vs baseline: 1.3451x; 1.0276x over previous
#include <cuda_runtime.h>
#include <cuda_bf16.h>

// ---------------------------------------------------------------------------
// GNN15: two GAT branches (int: 400K edges deg~4, nh: 1.6M edges deg~16)
// over 100K nodes, HEADS=3, FILT=16, then attention pooling to a scalar.
//
// R5: atomic-free GATHER aggregation.
//   build:   srcs[dst*CAP + atomicAdd(cnt[dst],1)] = src   (bucketed CSR,
//            fixed capacity, no scan/sort)
//   consume: one 8-lane octet per dst row; register accumulation of
//            sum(p*h[src]) and sum(p); single plain store per row.
//   out[d] = raw / (den + eps) applied in pooling.
// ---------------------------------------------------------------------------

#define NN      100000
#define E_INT   400000
#define E_NH    1600000
#define VF      11
#define HEADS   3
#define HF      48       // HEADS*FILT
#define RS      64       // row stride (floats) = 256B, 128B-aligned
#define XDIM    96       // 2*HF
#define CAP0    32       // bucket capacity, int branch (mean deg 4)
#define CAP1    64       // bucket capacity, nh branch  (mean deg 16)

// ---------------- scratch (static device globals; no allocation) -----------
__device__ __align__(256) float g_h0[NN * RS];     // h[0..47], es @ slot12
__device__ __align__(256) float g_h1[NN * RS];
__device__ __align__(16) float4 g_ed4_0[NN];
__device__ __align__(16) float4 g_ed4_1[NN];
__device__ __align__(256) float g_out0[NN * RS];   // raw sums, den @ slot12
__device__ __align__(256) float g_out1[NN * RS];
__device__ int g_cnt0[NN];
__device__ int g_cnt1[NN];
__device__ int g_srcs0[NN * CAP0];
__device__ int g_srcs1[NN * CAP1];
__device__ float g_acc[8];                         // num[3], den[3]
__device__ int   g_is64[2];

// ---------------- init: zero counters + detect edge dtype ------------------
// jax "int64" edges are int32 unless x64 is enabled. Values < 1e5 << 2^31,
// so if truly int64 every odd int32 word is 0. Check 16 of them.
__global__ void init_kernel(const void* e0, const void* e1) {
    int i = blockIdx.x * blockDim.x + threadIdx.x;
    int stride = gridDim.x * blockDim.x;
    for (int k = i; k < NN; k += stride) { g_cnt0[k] = 0; g_cnt1[k] = 0; }
    if (i == 0) {
        const int* a = (const int*)e0;
        const int* b = (const int*)e1;
        int is64a = 1, is64b = 1;
        #pragma unroll
        for (int t = 0; t < 16; t++) {
            if (a[2 * t + 1] != 0) is64a = 0;
            if (b[2 * t + 1] != 0) is64b = 0;
        }
        g_is64[0] = is64a;
        g_is64[1] = is64b;
        #pragma unroll
        for (int t = 0; t < 8; t++) g_acc[t] = 0.0f;
    }
}

// ---------------- node transform -------------------------------------------
__global__ void node_kernel(const float* __restrict__ feats,
                            const float* __restrict__ W0,
                            const float* __restrict__ as0, const float* __restrict__ ad0,
                            const float* __restrict__ W1,
                            const float* __restrict__ as1, const float* __restrict__ ad1) {
    __shared__ float sW[2][VF * HF];
    __shared__ float sAs[2][HF];
    __shared__ float sAd[2][HF];
    int tid = threadIdx.x;
    for (int i = tid; i < VF * HF; i += blockDim.x) { sW[0][i] = W0[i]; sW[1][i] = W1[i]; }
    for (int i = tid; i < HF; i += blockDim.x) {
        sAs[0][i] = as0[i]; sAd[0][i] = ad0[i];
        sAs[1][i] = as1[i]; sAd[1][i] = ad1[i];
    }
    __syncthreads();

    int n = blockIdx.x * blockDim.x + tid;
    if (n >= NN) return;

    float x[VF];
    #pragma unroll
    for (int k = 0; k < VF; k++) x[k] = feats[(size_t)n * VF + k];

    #pragma unroll
    for (int b = 0; b < 2; b++) {
        float* hout = (b == 0 ? g_h0 : g_h1) + (size_t)n * RS;
        float es[HEADS] = {0.f, 0.f, 0.f};
        float ed[HEADS] = {0.f, 0.f, 0.f};
        #pragma unroll
        for (int j = 0; j < HF; j++) {
            float s = 0.f;
            #pragma unroll
            for (int k = 0; k < VF; k++) s += x[k] * sW[b][k * HF + j];
            hout[j] = s;
            int hh = j >> 4;
            es[hh] += s * sAs[b][j];
            ed[hh] += s * sAd[b][j];
        }
        ((float4*)hout)[12] = make_float4(es[0], es[1], es[2], 0.f);   // es @ slot 12
        (b == 0 ? g_ed4_0 : g_ed4_1)[n] = make_float4(ed[0], ed[1], ed[2], 0.f);
    }
}

// ---------------- fill: bucketed CSR build (both branches, one launch) -----
__global__ void fill_kernel(const void* __restrict__ e0, const void* __restrict__ e1) {
    int t = blockIdx.x * blockDim.x + threadIdx.x;
    if (t < E_INT) {
        int e = t, s, d;
        if (g_is64[0]) {
            const long long* E64 = (const long long*)e0;
            s = (int)E64[e]; d = (int)E64[E_INT + e];
        } else {
            const int* E32 = (const int*)e0;
            s = E32[e]; d = E32[E_INT + e];
        }
        int pos = atomicAdd(&g_cnt0[d], 1);
        if (pos < CAP0) g_srcs0[d * CAP0 + pos] = s;
    } else if (t < E_INT + E_NH) {
        int e = t - E_INT, s, d;
        if (g_is64[1]) {
            const long long* E64 = (const long long*)e1;
            s = (int)E64[e]; d = (int)E64[E_NH + e];
        } else {
            const int* E32 = (const int*)e1;
            s = E32[e]; d = E32[E_NH + e];
        }
        int pos = atomicAdd(&g_cnt1[d], 1);
        if (pos < CAP1) g_srcs1[d * CAP1 + pos] = s;
    }
}

// ---------------- consume: 8-lane octet per dst row, register accum --------
// Per edge: hA = row bytes 0..127 (1 wf); hB = bytes 128..255 (1 wf), where
// lanes 0-3 read h slots 8..11 and lanes 4-7 read the es float4 (slot 12);
// es broadcast to the octet via width-8 shuffles. Plain store at end.
__global__ void __launch_bounds__(256) consume_kernel() {
    int t = blockIdx.x * blockDim.x + threadIdx.x;
    int oc = t >> 3, sub = t & 7;
    if (oc >= 2 * NN) return;

    const float* h;
    const int* srcs;
    float4 ed;
    float* orow;
    int deg;
    if (oc < NN) {
        int r = oc;
        h = g_h0; srcs = g_srcs0 + (size_t)r * CAP0;
        ed = g_ed4_0[r]; orow = g_out0 + (size_t)r * RS;
        deg = g_cnt0[r]; deg = deg < CAP0 ? deg : CAP0;
    } else {
        int r = oc - NN;
        h = g_h1; srcs = g_srcs1 + (size_t)r * CAP1;
        ed = g_ed4_1[r]; orow = g_out1 + (size_t)r * RS;
        deg = g_cnt1[r]; deg = deg < CAP1 ? deg : CAP1;
    }

    unsigned octmask = 0xFFu << (threadIdx.x & 24);   // this octet's lanes

    float4 acc0 = make_float4(0.f, 0.f, 0.f, 0.f);
    float4 acc1 = make_float4(0.f, 0.f, 0.f, 0.f);
    float d0 = 0.f, d1 = 0.f, d2 = 0.f;

    #pragma unroll 2
    for (int i = 0; i < deg; i++) {
        int s = srcs[i];
        const float4* hr = (const float4*)(h + (size_t)s * RS);
        float4 hA = hr[sub];
        float4 hB = hr[sub < 4 ? 8 + sub : 12];
        float esx = __shfl_sync(octmask, hB.x, 4, 8);
        float esy = __shfl_sync(octmask, hB.y, 4, 8);
        float esz = __shfl_sync(octmask, hB.z, 4, 8);
        float v0 = esx + ed.x, v1 = esy + ed.y, v2 = esz + ed.z;
        v0 = v0 > 0.f ? v0 : 0.2f * v0;        // leaky_relu(0.2)
        v1 = v1 > 0.f ? v1 : 0.2f * v1;
        v2 = v2 > 0.f ? v2 : 0.2f * v2;
        float p0 = __expf(v0);                 // no max-shift needed (|v| small)
        float p1 = __expf(v1);
        float p2 = __expf(v2);
        float pa = sub < 4 ? p0 : p1;
        acc0.x += pa * hA.x; acc0.y += pa * hA.y;
        acc0.z += pa * hA.z; acc0.w += pa * hA.w;
        if (sub < 4) {
            acc1.x += p2 * hB.x; acc1.y += p2 * hB.y;
            acc1.z += p2 * hB.z; acc1.w += p2 * hB.w;
        }
        d0 += p0; d1 += p1; d2 += p2;
    }

    float4* or4 = (float4*)orow;
    or4[sub] = acc0;                                   // bytes 0..127
    if (sub < 4) or4[8 + sub] = acc1;                  // bytes 128..191
    if (sub == 4) or4[12] = make_float4(d0, d1, d2, 0.f);  // den @ slot 12
}

// ---------------- pooling: normalize + fused tanh-attention reduction ------
// x_n[d] = raw[n][d] / (den[n][head(d)] + 1e-16)
// out = sum_h ( sum_n e^{tanh(x_n . attw_h)} * (x_n . dw_h) )
//             / ( sum_n e^{tanh(x_n . attw_h)} )  + b
__global__ void pool_kernel(const float* __restrict__ attw,
                            const float* __restrict__ dw) {
    __shared__ float sA[XDIM * HEADS];   // attw: [96,3] row-major
    __shared__ float sD[XDIM * HEADS];   // dense_w: [288] = [3][96] h-major
    int tid = threadIdx.x;
    for (int i = tid; i < XDIM * HEADS; i += blockDim.x) { sA[i] = attw[i]; sD[i] = dw[i]; }
    __syncthreads();

    int n = blockIdx.x * blockDim.x + tid;
    float sh[HEADS] = {0.f, 0.f, 0.f};
    float dh[HEADS] = {0.f, 0.f, 0.f};
    if (n < NN) {
        const float4* x0 = (const float4*)(g_out0 + (size_t)n * RS);
        const float4* x1 = (const float4*)(g_out1 + (size_t)n * RS);
        float4 dn0 = x0[12];
        float4 dn1 = x1[12];
        float inv0[HEADS] = {1.f / (dn0.x + 1e-16f), 1.f / (dn0.y + 1e-16f), 1.f / (dn0.z + 1e-16f)};
        float inv1[HEADS] = {1.f / (dn1.x + 1e-16f), 1.f / (dn1.y + 1e-16f), 1.f / (dn1.z + 1e-16f)};
        #pragma unroll
        for (int j = 0; j < HF / 4; j++) {
            float4 v0 = x0[j];
            float4 v1 = x1[j];
            int hh = j >> 2;
            float q0[4] = {v0.x * inv0[hh], v0.y * inv0[hh], v0.z * inv0[hh], v0.w * inv0[hh]};
            float q1[4] = {v1.x * inv1[hh], v1.y * inv1[hh], v1.z * inv1[hh], v1.w * inv1[hh]};
            #pragma unroll
            for (int c = 0; c < 4; c++) {
                int dA = j * 4 + c;
                int dB = dA + HF;
                #pragma unroll
                for (int h = 0; h < HEADS; h++) {
                    sh[h] += q0[c] * sA[dA * HEADS + h] + q1[c] * sA[dB * HEADS + h];
                    dh[h] += q0[c] * sD[h * XDIM + dA] + q1[c] * sD[h * XDIM + dB];
                }
            }
        }
    }
    float num[HEADS], den[HEADS];
    #pragma unroll
    for (int h = 0; h < HEADS; h++) {
        float w = (n < NN) ? __expf(tanhf(sh[h])) : 0.f;
        num[h] = w * dh[h];
        den[h] = w;
    }
    #pragma unroll
    for (int off = 16; off > 0; off >>= 1) {
        #pragma unroll
        for (int h = 0; h < HEADS; h++) {
            num[h] += __shfl_down_sync(0xFFFFFFFFu, num[h], off);
            den[h] += __shfl_down_sync(0xFFFFFFFFu, den[h], off);
        }
    }
    if ((tid & 31) == 0) {
        #pragma unroll
        for (int h = 0; h < HEADS; h++) {
            atomicAdd(&g_acc[h], num[h]);
            atomicAdd(&g_acc[HEADS + h], den[h]);
        }
    }
}

__global__ void finalize_kernel(const float* __restrict__ bias, float* __restrict__ out) {
    float r = 0.f;
    #pragma unroll
    for (int h = 0; h < HEADS; h++) r += g_acc[h] / g_acc[HEADS + h];
    out[0] = r + bias[0];
}

// ---------------------------------------------------------------------------
extern "C" void kernel_launch(void* const* d_in, const int* in_sizes, int n_in,
                              void* d_out, int out_size) {
    const float* node_feats = (const float*)d_in[0];
    const float* W_int   = (const float*)d_in[1];
    const float* asrc_i  = (const float*)d_in[2];
    const float* adst_i  = (const float*)d_in[3];
    const float* W_nh    = (const float*)d_in[4];
    const float* asrc_n  = (const float*)d_in[5];
    const float* adst_n  = (const float*)d_in[6];
    const float* att_w   = (const float*)d_in[7];
    const float* dense_w = (const float*)d_in[8];
    const float* dense_b = (const float*)d_in[9];
    const void*  edge_i  = d_in[10];
    const void*  edge_n  = d_in[11];
    float* out = (float*)d_out;

    init_kernel<<<128, 256>>>(edge_i, edge_n);
    node_kernel<<<(NN + 255) / 256, 256>>>(node_feats, W_int, asrc_i, adst_i,
                                           W_nh, asrc_n, adst_n);
    fill_kernel<<<(E_INT + E_NH + 255) / 256, 256>>>(edge_i, edge_n);
    consume_kernel<<<(2 * NN * 8 + 255) / 256, 256>>>();
    pool_kernel<<<(NN + 255) / 256, 256>>>(att_w, dense_w);
    finalize_kernel<<<1, 1>>>(dense_b, out);
}

// round 6
// speedup vs baseline: 1.3800x; 1.0260x over previous
#include <cuda_runtime.h>
#include <cuda_bf16.h>

// ---------------------------------------------------------------------------
// GNN15: two GAT branches (int: 400K edges deg~4, nh: 1.6M edges deg~16)
// over 100K nodes, HEADS=3, FILT=16, then attention pooling to a scalar.
//
// R6: gather consume with 4-edge batched MLP.
//   build:   srcs[dst*CAP + atomicAdd(cnt[dst],1)] = src   (bucketed CSR)
//   consume: one 8-lane octet per dst row; int4 src loads; 4 edges' h-rows
//            gathered before accumulation (MLP ~8/thread); plain store.
//   out[d] = raw / (den + eps) applied in pooling.
// ---------------------------------------------------------------------------

#define NN      100000
#define E_INT   400000
#define E_NH    1600000
#define VF      11
#define HEADS   3
#define HF      48       // HEADS*FILT
#define RS      64       // row stride (floats) = 256B, 128B-aligned
#define XDIM    96       // 2*HF
#define CAP0    32       // bucket capacity, int branch (mean deg 4)
#define CAP1    64       // bucket capacity, nh branch  (mean deg 16)

// ---------------- scratch (static device globals; no allocation) -----------
__device__ __align__(256) float g_h0[NN * RS];     // h[0..47], es @ slot12
__device__ __align__(256) float g_h1[NN * RS];
__device__ __align__(16) float4 g_ed4_0[NN];
__device__ __align__(16) float4 g_ed4_1[NN];
__device__ __align__(256) float g_out0[NN * RS];   // raw sums, den @ slot12
__device__ __align__(256) float g_out1[NN * RS];
__device__ int g_cnt0[NN];
__device__ int g_cnt1[NN];
__device__ __align__(16) int g_srcs0[NN * CAP0];
__device__ __align__(16) int g_srcs1[NN * CAP1];
__device__ float g_acc[8];                         // num[3], den[3]
__device__ int   g_is64[2];

// ---------------- init: zero counters + detect edge dtype ------------------
// jax "int64" edges are int32 unless x64 is enabled. Values < 1e5 << 2^31,
// so if truly int64 every odd int32 word is 0. Check 16 of them.
__global__ void init_kernel(const void* e0, const void* e1) {
    int i = blockIdx.x * blockDim.x + threadIdx.x;
    int stride = gridDim.x * blockDim.x;
    for (int k = i; k < NN; k += stride) { g_cnt0[k] = 0; g_cnt1[k] = 0; }
    if (i == 0) {
        const int* a = (const int*)e0;
        const int* b = (const int*)e1;
        int is64a = 1, is64b = 1;
        #pragma unroll
        for (int t = 0; t < 16; t++) {
            if (a[2 * t + 1] != 0) is64a = 0;
            if (b[2 * t + 1] != 0) is64b = 0;
        }
        g_is64[0] = is64a;
        g_is64[1] = is64b;
        #pragma unroll
        for (int t = 0; t < 8; t++) g_acc[t] = 0.0f;
    }
}

// ---------------- node transform -------------------------------------------
__global__ void node_kernel(const float* __restrict__ feats,
                            const float* __restrict__ W0,
                            const float* __restrict__ as0, const float* __restrict__ ad0,
                            const float* __restrict__ W1,
                            const float* __restrict__ as1, const float* __restrict__ ad1) {
    __shared__ float sW[2][VF * HF];
    __shared__ float sAs[2][HF];
    __shared__ float sAd[2][HF];
    int tid = threadIdx.x;
    for (int i = tid; i < VF * HF; i += blockDim.x) { sW[0][i] = W0[i]; sW[1][i] = W1[i]; }
    for (int i = tid; i < HF; i += blockDim.x) {
        sAs[0][i] = as0[i]; sAd[0][i] = ad0[i];
        sAs[1][i] = as1[i]; sAd[1][i] = ad1[i];
    }
    __syncthreads();

    int n = blockIdx.x * blockDim.x + tid;
    if (n >= NN) return;

    float x[VF];
    #pragma unroll
    for (int k = 0; k < VF; k++) x[k] = feats[(size_t)n * VF + k];

    #pragma unroll
    for (int b = 0; b < 2; b++) {
        float* hout = (b == 0 ? g_h0 : g_h1) + (size_t)n * RS;
        float es[HEADS] = {0.f, 0.f, 0.f};
        float ed[HEADS] = {0.f, 0.f, 0.f};
        #pragma unroll
        for (int j = 0; j < HF; j++) {
            float s = 0.f;
            #pragma unroll
            for (int k = 0; k < VF; k++) s += x[k] * sW[b][k * HF + j];
            hout[j] = s;
            int hh = j >> 4;
            es[hh] += s * sAs[b][j];
            ed[hh] += s * sAd[b][j];
        }
        ((float4*)hout)[12] = make_float4(es[0], es[1], es[2], 0.f);   // es @ slot 12
        (b == 0 ? g_ed4_0 : g_ed4_1)[n] = make_float4(ed[0], ed[1], ed[2], 0.f);
    }
}

// ---------------- fill: bucketed CSR build (both branches, one launch) -----
__global__ void fill_kernel(const void* __restrict__ e0, const void* __restrict__ e1) {
    int t = blockIdx.x * blockDim.x + threadIdx.x;
    if (t < E_INT) {
        int e = t, s, d;
        if (g_is64[0]) {
            const long long* E64 = (const long long*)e0;
            s = (int)E64[e]; d = (int)E64[E_INT + e];
        } else {
            const int* E32 = (const int*)e0;
            s = E32[e]; d = E32[E_INT + e];
        }
        int pos = atomicAdd(&g_cnt0[d], 1);
        if (pos < CAP0) g_srcs0[d * CAP0 + pos] = s;
    } else if (t < E_INT + E_NH) {
        int e = t - E_INT, s, d;
        if (g_is64[1]) {
            const long long* E64 = (const long long*)e1;
            s = (int)E64[e]; d = (int)E64[E_NH + e];
        } else {
            const int* E32 = (const int*)e1;
            s = E32[e]; d = E32[E_NH + e];
        }
        int pos = atomicAdd(&g_cnt1[d], 1);
        if (pos < CAP1) g_srcs1[d * CAP1 + pos] = s;
    }
}

// ---------------- consume: octet per dst row, 4-edge batched gathers -------
__device__ __forceinline__ void edge_acc(float4 hA, float4 hB, float4 ed,
                                         unsigned octmask, int sub,
                                         float4& acc0, float4& acc1,
                                         float& d0, float& d1, float& d2) {
    float esx = __shfl_sync(octmask, hB.x, 4, 8);
    float esy = __shfl_sync(octmask, hB.y, 4, 8);
    float esz = __shfl_sync(octmask, hB.z, 4, 8);
    float v0 = esx + ed.x, v1 = esy + ed.y, v2 = esz + ed.z;
    v0 = v0 > 0.f ? v0 : 0.2f * v0;        // leaky_relu(0.2)
    v1 = v1 > 0.f ? v1 : 0.2f * v1;
    v2 = v2 > 0.f ? v2 : 0.2f * v2;
    float p0 = __expf(v0);                 // no max-shift needed (|v| small)
    float p1 = __expf(v1);
    float p2 = __expf(v2);
    float pa = sub < 4 ? p0 : p1;
    acc0.x += pa * hA.x; acc0.y += pa * hA.y;
    acc0.z += pa * hA.z; acc0.w += pa * hA.w;
    if (sub < 4) {
        acc1.x += p2 * hB.x; acc1.y += p2 * hB.y;
        acc1.z += p2 * hB.z; acc1.w += p2 * hB.w;
    }
    d0 += p0; d1 += p1; d2 += p2;
}

__global__ void __launch_bounds__(256) consume_kernel() {
    int t = blockIdx.x * blockDim.x + threadIdx.x;
    int oc = t >> 3, sub = t & 7;
    if (oc >= 2 * NN) return;

    const float* h;
    const int* srcs;
    float4 ed;
    float* orow;
    int deg;
    if (oc < NN) {
        int r = oc;
        h = g_h0; srcs = g_srcs0 + (size_t)r * CAP0;
        ed = g_ed4_0[r]; orow = g_out0 + (size_t)r * RS;
        deg = g_cnt0[r]; deg = deg < CAP0 ? deg : CAP0;
    } else {
        int r = oc - NN;
        h = g_h1; srcs = g_srcs1 + (size_t)r * CAP1;
        ed = g_ed4_1[r]; orow = g_out1 + (size_t)r * RS;
        deg = g_cnt1[r]; deg = deg < CAP1 ? deg : CAP1;
    }

    int subB = sub < 4 ? 8 + sub : 12;
    unsigned octmask = 0xFFu << (threadIdx.x & 24);   // this octet's lanes

    float4 acc0 = make_float4(0.f, 0.f, 0.f, 0.f);
    float4 acc1 = make_float4(0.f, 0.f, 0.f, 0.f);
    float d0 = 0.f, d1 = 0.f, d2 = 0.f;

    int i = 0;
    for (; i + 4 <= deg; i += 4) {
        int4 s4 = *(const int4*)(srcs + i);            // 16B-aligned bucket
        const float4* r0 = (const float4*)(h + (size_t)s4.x * RS);
        const float4* r1 = (const float4*)(h + (size_t)s4.y * RS);
        const float4* r2 = (const float4*)(h + (size_t)s4.z * RS);
        const float4* r3 = (const float4*)(h + (size_t)s4.w * RS);
        // issue all 8 gathers before consuming any (MLP ~8/thread)
        float4 A0 = r0[sub], B0 = r0[subB];
        float4 A1 = r1[sub], B1 = r1[subB];
        float4 A2 = r2[sub], B2 = r2[subB];
        float4 A3 = r3[sub], B3 = r3[subB];
        edge_acc(A0, B0, ed, octmask, sub, acc0, acc1, d0, d1, d2);
        edge_acc(A1, B1, ed, octmask, sub, acc0, acc1, d0, d1, d2);
        edge_acc(A2, B2, ed, octmask, sub, acc0, acc1, d0, d1, d2);
        edge_acc(A3, B3, ed, octmask, sub, acc0, acc1, d0, d1, d2);
    }
    for (; i < deg; i++) {
        int s = srcs[i];
        const float4* hr = (const float4*)(h + (size_t)s * RS);
        float4 hA = hr[sub];
        float4 hB = hr[subB];
        edge_acc(hA, hB, ed, octmask, sub, acc0, acc1, d0, d1, d2);
    }

    float4* or4 = (float4*)orow;
    or4[sub] = acc0;                                   // bytes 0..127
    if (sub < 4) or4[8 + sub] = acc1;                  // bytes 128..191
    if (sub == 4) or4[12] = make_float4(d0, d1, d2, 0.f);  // den @ slot 12
}

// ---------------- pooling: normalize + fused tanh-attention reduction ------
// x_n[d] = raw[n][d] / (den[n][head(d)] + 1e-16)
// out = sum_h ( sum_n e^{tanh(x_n . attw_h)} * (x_n . dw_h) )
//             / ( sum_n e^{tanh(x_n . attw_h)} )  + b
__global__ void pool_kernel(const float* __restrict__ attw,
                            const float* __restrict__ dw) {
    __shared__ float sA[XDIM * HEADS];   // attw: [96,3] row-major
    __shared__ float sD[XDIM * HEADS];   // dense_w: [288] = [3][96] h-major
    int tid = threadIdx.x;
    for (int i = tid; i < XDIM * HEADS; i += blockDim.x) { sA[i] = attw[i]; sD[i] = dw[i]; }
    __syncthreads();

    int n = blockIdx.x * blockDim.x + tid;
    float sh[HEADS] = {0.f, 0.f, 0.f};
    float dh[HEADS] = {0.f, 0.f, 0.f};
    if (n < NN) {
        const float4* x0 = (const float4*)(g_out0 + (size_t)n * RS);
        const float4* x1 = (const float4*)(g_out1 + (size_t)n * RS);
        float4 dn0 = x0[12];
        float4 dn1 = x1[12];
        float inv0[HEADS] = {1.f / (dn0.x + 1e-16f), 1.f / (dn0.y + 1e-16f), 1.f / (dn0.z + 1e-16f)};
        float inv1[HEADS] = {1.f / (dn1.x + 1e-16f), 1.f / (dn1.y + 1e-16f), 1.f / (dn1.z + 1e-16f)};
        #pragma unroll
        for (int j = 0; j < HF / 4; j++) {
            float4 v0 = x0[j];
            float4 v1 = x1[j];
            int hh = j >> 2;
            float q0[4] = {v0.x * inv0[hh], v0.y * inv0[hh], v0.z * inv0[hh], v0.w * inv0[hh]};
            float q1[4] = {v1.x * inv1[hh], v1.y * inv1[hh], v1.z * inv1[hh], v1.w * inv1[hh]};
            #pragma unroll
            for (int c = 0; c < 4; c++) {
                int dA = j * 4 + c;
                int dB = dA + HF;
                #pragma unroll
                for (int h = 0; h < HEADS; h++) {
                    sh[h] += q0[c] * sA[dA * HEADS + h] + q1[c] * sA[dB * HEADS + h];
                    dh[h] += q0[c] * sD[h * XDIM + dA] + q1[c] * sD[h * XDIM + dB];
                }
            }
        }
    }
    float num[HEADS], den[HEADS];
    #pragma unroll
    for (int h = 0; h < HEADS; h++) {
        float w = (n < NN) ? __expf(tanhf(sh[h])) : 0.f;
        num[h] = w * dh[h];
        den[h] = w;
    }
    #pragma unroll
    for (int off = 16; off > 0; off >>= 1) {
        #pragma unroll
        for (int h = 0; h < HEADS; h++) {
            num[h] += __shfl_down_sync(0xFFFFFFFFu, num[h], off);
            den[h] += __shfl_down_sync(0xFFFFFFFFu, den[h], off);
        }
    }
    if ((tid & 31) == 0) {
        #pragma unroll
        for (int h = 0; h < HEADS; h++) {
            atomicAdd(&g_acc[h], num[h]);
            atomicAdd(&g_acc[HEADS + h], den[h]);
        }
    }
}

__global__ void finalize_kernel(const float* __restrict__ bias, float* __restrict__ out) {
    float r = 0.f;
    #pragma unroll
    for (int h = 0; h < HEADS; h++) r += g_acc[h] / g_acc[HEADS + h];
    out[0] = r + bias[0];
}

// ---------------------------------------------------------------------------
extern "C" void kernel_launch(void* const* d_in, const int* in_sizes, int n_in,
                              void* d_out, int out_size) {
    const float* node_feats = (const float*)d_in[0];
    const float* W_int   = (const float*)d_in[1];
    const float* asrc_i  = (const float*)d_in[2];
    const float* adst_i  = (const float*)d_in[3];
    const float* W_nh    = (const float*)d_in[4];
    const float* asrc_n  = (const float*)d_in[5];
    const float* adst_n  = (const float*)d_in[6];
    const float* att_w   = (const float*)d_in[7];
    const float* dense_w = (const float*)d_in[8];
    const float* dense_b = (const float*)d_in[9];
    const void*  edge_i  = d_in[10];
    const void*  edge_n  = d_in[11];
    float* out = (float*)d_out;

    init_kernel<<<128, 256>>>(edge_i, edge_n);
    node_kernel<<<(NN + 255) / 256, 256>>>(node_feats, W_int, asrc_i, adst_i,
                                           W_nh, asrc_n, adst_n);
    fill_kernel<<<(E_INT + E_NH + 255) / 256, 256>>>(edge_i, edge_n);
    consume_kernel<<<(2 * NN * 8 + 255) / 256, 256>>>();
    pool_kernel<<<(NN + 255) / 256, 256>>>(att_w, dense_w);
    finalize_kernel<<<1, 1>>>(dense_b, out);
}

// round 8
// speedup vs baseline: 1.4593x; 1.0575x over previous
#include <cuda_runtime.h>
#include <cuda_bf16.h>

// ---------------------------------------------------------------------------
// GNN15: two GAT branches (int: 400K edges deg~4, nh: 1.6M edges deg~16)
// over 100K nodes, HEADS=3, FILT=16, then attention pooling to a scalar.
//
// R8: R6's correct 256B-row gather layout (h[0..47] + log2e-scaled es @ slot
// 12) + occupancy fix (launch_bounds 256,4), ex2.approx, self-resetting
// counters (no init kernel), 2-edge vectorized fill.
//   out[d] = raw / (den + eps) applied in pooling.
// ---------------------------------------------------------------------------

#define NN      100000
#define E_INT   400000
#define E_NH    1600000
#define VF      11
#define HEADS   3
#define HF      48
#define RS      64       // row stride (floats) = 256B, 128B-aligned
#define XDIM    96
#define CAP0    32
#define CAP1    64
#define LOG2E   1.4426950408889634f

// ---------------- scratch (static device globals; no allocation) -----------
__device__ __align__(256) float g_h0[NN * RS];     // h[0..47], es*log2e @ slot12
__device__ __align__(256) float g_h1[NN * RS];
__device__ __align__(16) float4 g_ed4_0[NN];       // ed*log2e
__device__ __align__(16) float4 g_ed4_1[NN];
__device__ __align__(256) float g_out0[NN * RS];   // raw sums, den @ slot12
__device__ __align__(256) float g_out1[NN * RS];
__device__ int g_cnt0[NN];                          // zero-init; self-resetting
__device__ int g_cnt1[NN];
__device__ __align__(16) int g_srcs0[NN * CAP0];
__device__ __align__(16) int g_srcs1[NN * CAP1];
__device__ float g_acc[8];                          // num[3], den[3]; self-reset
__device__ int   g_is64[2];

__device__ __forceinline__ float ex2(float x) {
    float r;
    asm("ex2.approx.f32 %0, %1;" : "=f"(r) : "f"(x));
    return r;
}

// ---------------- detect edge dtype ----------------------------------------
// jax "int64" edges are int32 unless x64 is enabled. Values < 1e5 << 2^31,
// so if truly int64 every odd int32 word is 0. Check 16 of them.
__global__ void detect_kernel(const void* e0, const void* e1) {
    if (threadIdx.x == 0) {
        const int* a = (const int*)e0;
        const int* b = (const int*)e1;
        int is64a = 1, is64b = 1;
        #pragma unroll
        for (int t = 0; t < 16; t++) {
            if (a[2 * t + 1] != 0) is64a = 0;
            if (b[2 * t + 1] != 0) is64b = 0;
        }
        g_is64[0] = is64a;
        g_is64[1] = is64b;
    }
}

// ---------------- node transform -------------------------------------------
__global__ void node_kernel(const float* __restrict__ feats,
                            const float* __restrict__ W0,
                            const float* __restrict__ as0, const float* __restrict__ ad0,
                            const float* __restrict__ W1,
                            const float* __restrict__ as1, const float* __restrict__ ad1) {
    __shared__ float sW[2][VF * HF];
    __shared__ float sAs[2][HF];
    __shared__ float sAd[2][HF];
    int tid = threadIdx.x;
    for (int i = tid; i < VF * HF; i += blockDim.x) { sW[0][i] = W0[i]; sW[1][i] = W1[i]; }
    for (int i = tid; i < HF; i += blockDim.x) {
        sAs[0][i] = as0[i]; sAd[0][i] = ad0[i];
        sAs[1][i] = as1[i]; sAd[1][i] = ad1[i];
    }
    __syncthreads();

    int n = blockIdx.x * blockDim.x + tid;
    if (n >= NN) return;

    float x[VF];
    #pragma unroll
    for (int k = 0; k < VF; k++) x[k] = feats[(size_t)n * VF + k];

    #pragma unroll
    for (int b = 0; b < 2; b++) {
        float* hout = (b == 0 ? g_h0 : g_h1) + (size_t)n * RS;
        float es[HEADS] = {0.f, 0.f, 0.f};
        float ed[HEADS] = {0.f, 0.f, 0.f};
        #pragma unroll
        for (int j = 0; j < HF; j++) {
            float s = 0.f;
            #pragma unroll
            for (int k = 0; k < VF; k++) s += x[k] * sW[b][k * HF + j];
            hout[j] = s;
            int hh = j >> 4;
            es[hh] += s * sAs[b][j];
            ed[hh] += s * sAd[b][j];
        }
        // es, ed pre-scaled by log2e so consume can use ex2 directly;
        // leaky_relu is positively homogeneous so lrelu(c*x) = c*lrelu(x).
        ((float4*)hout)[12] = make_float4(es[0] * LOG2E, es[1] * LOG2E, es[2] * LOG2E, 0.f);
        (b == 0 ? g_ed4_0 : g_ed4_1)[n] =
            make_float4(ed[0] * LOG2E, ed[1] * LOG2E, ed[2] * LOG2E, 0.f);
    }
}

// ---------------- fill: bucketed CSR build, 2 edges/thread -----------------
__global__ void fill_kernel(const void* __restrict__ e0, const void* __restrict__ e1) {
    int t = blockIdx.x * blockDim.x + threadIdx.x;
    const int H0 = E_INT / 2, H1 = E_NH / 2;
    if (t < H0) {
        int s0, s1, d0, d1;
        if (g_is64[0]) {
            const longlong2* p = (const longlong2*)e0;
            longlong2 sv = p[t];
            longlong2 dv = p[H0 + t];
            s0 = (int)sv.x; s1 = (int)sv.y; d0 = (int)dv.x; d1 = (int)dv.y;
        } else {
            const int2* p = (const int2*)e0;
            int2 sv = p[t];
            int2 dv = p[H0 + t];
            s0 = sv.x; s1 = sv.y; d0 = dv.x; d1 = dv.y;
        }
        int p0 = atomicAdd(&g_cnt0[d0], 1);
        if (p0 < CAP0) g_srcs0[d0 * CAP0 + p0] = s0;
        int p1 = atomicAdd(&g_cnt0[d1], 1);
        if (p1 < CAP0) g_srcs0[d1 * CAP0 + p1] = s1;
    } else if (t < H0 + H1) {
        int u = t - H0;
        int s0, s1, d0, d1;
        if (g_is64[1]) {
            const longlong2* p = (const longlong2*)e1;
            longlong2 sv = p[u];
            longlong2 dv = p[H1 + u];
            s0 = (int)sv.x; s1 = (int)sv.y; d0 = (int)dv.x; d1 = (int)dv.y;
        } else {
            const int2* p = (const int2*)e1;
            int2 sv = p[u];
            int2 dv = p[H1 + u];
            s0 = sv.x; s1 = sv.y; d0 = dv.x; d1 = dv.y;
        }
        int p0 = atomicAdd(&g_cnt1[d0], 1);
        if (p0 < CAP1) g_srcs1[d0 * CAP1 + p0] = s0;
        int p1 = atomicAdd(&g_cnt1[d1], 1);
        if (p1 < CAP1) g_srcs1[d1 * CAP1 + p1] = s1;
    }
}

// ---------------- consume: octet per dst row, 4-edge batched gathers -------
__device__ __forceinline__ void edge_acc(float4 hA, float4 hB, float4 ed,
                                         unsigned octmask, int sub,
                                         float4& acc0, float4& acc1,
                                         float& d0, float& d1, float& d2) {
    float esx = __shfl_sync(octmask, hB.x, 4, 8);    // lane base+4 holds es
    float esy = __shfl_sync(octmask, hB.y, 4, 8);
    float esz = __shfl_sync(octmask, hB.z, 4, 8);
    float v0 = esx + ed.x, v1 = esy + ed.y, v2 = esz + ed.z;
    v0 = v0 > 0.f ? v0 : 0.2f * v0;        // leaky_relu(0.2), log2-domain
    v1 = v1 > 0.f ? v1 : 0.2f * v1;
    v2 = v2 > 0.f ? v2 : 0.2f * v2;
    float p0 = ex2(v0);                    // = exp(lrelu(raw)), exact commute
    float p1 = ex2(v1);
    float p2 = ex2(v2);
    float pa = sub < 4 ? p0 : p1;
    acc0.x += pa * hA.x; acc0.y += pa * hA.y;
    acc0.z += pa * hA.z; acc0.w += pa * hA.w;
    if (sub < 4) {
        acc1.x += p2 * hB.x; acc1.y += p2 * hB.y;
        acc1.z += p2 * hB.z; acc1.w += p2 * hB.w;
    }
    d0 += p0; d1 += p1; d2 += p2;
}

__global__ void __launch_bounds__(256, 4) consume_kernel() {
    int t = blockIdx.x * blockDim.x + threadIdx.x;
    int oc = t >> 3, sub = t & 7;
    if (oc >= 2 * NN) return;

    const float* h;
    const int* srcs;
    float4 ed;
    float* orow;
    int* cntp;
    int cap;
    if (oc < NN) {
        int r = oc;
        h = g_h0; srcs = g_srcs0 + (size_t)r * CAP0;
        ed = g_ed4_0[r]; orow = g_out0 + (size_t)r * RS;
        cntp = &g_cnt0[r]; cap = CAP0;
    } else {
        int r = oc - NN;
        h = g_h1; srcs = g_srcs1 + (size_t)r * CAP1;
        ed = g_ed4_1[r]; orow = g_out1 + (size_t)r * RS;
        cntp = &g_cnt1[r]; cap = CAP1;
    }

    int deg = *cntp;
    deg = deg < cap ? deg : cap;

    int subB = sub < 4 ? 8 + sub : 12;     // lanes 0-3: head2 slots; 4-7: es
    unsigned octmask = 0xFFu << (threadIdx.x & 24);

    float4 acc0 = make_float4(0.f, 0.f, 0.f, 0.f);
    float4 acc1 = make_float4(0.f, 0.f, 0.f, 0.f);
    float d0 = 0.f, d1 = 0.f, d2 = 0.f;

    int i = 0;
    for (; i + 4 <= deg; i += 4) {
        int4 s4 = *(const int4*)(srcs + i);            // 16B-aligned bucket
        const float4* r0 = (const float4*)(h + (size_t)s4.x * RS);
        const float4* r1 = (const float4*)(h + (size_t)s4.y * RS);
        const float4* r2 = (const float4*)(h + (size_t)s4.z * RS);
        const float4* r3 = (const float4*)(h + (size_t)s4.w * RS);
        // issue all 8 gathers before consuming any (MLP ~8/thread)
        float4 A0 = r0[sub], B0 = r0[subB];
        float4 A1 = r1[sub], B1 = r1[subB];
        float4 A2 = r2[sub], B2 = r2[subB];
        float4 A3 = r3[sub], B3 = r3[subB];
        edge_acc(A0, B0, ed, octmask, sub, acc0, acc1, d0, d1, d2);
        edge_acc(A1, B1, ed, octmask, sub, acc0, acc1, d0, d1, d2);
        edge_acc(A2, B2, ed, octmask, sub, acc0, acc1, d0, d1, d2);
        edge_acc(A3, B3, ed, octmask, sub, acc0, acc1, d0, d1, d2);
    }
    for (; i < deg; i++) {
        int s = srcs[i];
        const float4* hr = (const float4*)(h + (size_t)s * RS);
        float4 hA = hr[sub];
        float4 hB = hr[subB];
        edge_acc(hA, hB, ed, octmask, sub, acc0, acc1, d0, d1, d2);
    }

    float4* or4 = (float4*)orow;
    or4[sub] = acc0;                                   // bytes 0..127
    if (sub < 4) or4[8 + sub] = acc1;                  // head 2
    if (sub == 4) or4[12] = make_float4(d0, d1, d2, 0.f);  // den @ slot 12
    if (sub == 5) *cntp = 0;                           // reset for next replay
}

// ---------------- pooling: normalize + fused tanh-attention reduction ------
// x_n[d] = raw[n][d] / (den[n][head(d)] + 1e-16)
// out = sum_h ( sum_n e^{tanh(x_n . attw_h)} * (x_n . dw_h) )
//             / ( sum_n e^{tanh(x_n . attw_h)} )  + b
__global__ void pool_kernel(const float* __restrict__ attw,
                            const float* __restrict__ dw) {
    __shared__ float sA[XDIM * HEADS];   // attw: [96,3] row-major
    __shared__ float sD[XDIM * HEADS];   // dense_w: [288] = [3][96] h-major
    int tid = threadIdx.x;
    for (int i = tid; i < XDIM * HEADS; i += blockDim.x) { sA[i] = attw[i]; sD[i] = dw[i]; }
    __syncthreads();

    int n = blockIdx.x * blockDim.x + tid;
    float sh[HEADS] = {0.f, 0.f, 0.f};
    float dh[HEADS] = {0.f, 0.f, 0.f};
    if (n < NN) {
        const float4* x0 = (const float4*)(g_out0 + (size_t)n * RS);
        const float4* x1 = (const float4*)(g_out1 + (size_t)n * RS);
        float4 dn0 = x0[12];
        float4 dn1 = x1[12];
        float inv0[HEADS] = {1.f / (dn0.x + 1e-16f), 1.f / (dn0.y + 1e-16f), 1.f / (dn0.z + 1e-16f)};
        float inv1[HEADS] = {1.f / (dn1.x + 1e-16f), 1.f / (dn1.y + 1e-16f), 1.f / (dn1.z + 1e-16f)};
        #pragma unroll
        for (int j = 0; j < HF / 4; j++) {
            float4 v0 = x0[j];
            float4 v1 = x1[j];
            int hh = j >> 2;
            float q0[4] = {v0.x * inv0[hh], v0.y * inv0[hh], v0.z * inv0[hh], v0.w * inv0[hh]};
            float q1[4] = {v1.x * inv1[hh], v1.y * inv1[hh], v1.z * inv1[hh], v1.w * inv1[hh]};
            #pragma unroll
            for (int c = 0; c < 4; c++) {
                int dA = j * 4 + c;
                int dB = dA + HF;
                #pragma unroll
                for (int h = 0; h < HEADS; h++) {
                    sh[h] += q0[c] * sA[dA * HEADS + h] + q1[c] * sA[dB * HEADS + h];
                    dh[h] += q0[c] * sD[h * XDIM + dA] + q1[c] * sD[h * XDIM + dB];
                }
            }
        }
    }
    float num[HEADS], den[HEADS];
    #pragma unroll
    for (int h = 0; h < HEADS; h++) {
        float w = (n < NN) ? __expf(tanhf(sh[h])) : 0.f;
        num[h] = w * dh[h];
        den[h] = w;
    }
    #pragma unroll
    for (int off = 16; off > 0; off >>= 1) {
        #pragma unroll
        for (int h = 0; h < HEADS; h++) {
            num[h] += __shfl_down_sync(0xFFFFFFFFu, num[h], off);
            den[h] += __shfl_down_sync(0xFFFFFFFFu, den[h], off);
        }
    }
    if ((tid & 31) == 0) {
        #pragma unroll
        for (int h = 0; h < HEADS; h++) {
            atomicAdd(&g_acc[h], num[h]);
            atomicAdd(&g_acc[HEADS + h], den[h]);
        }
    }
}

__global__ void finalize_kernel(const float* __restrict__ bias, float* __restrict__ out) {
    float r = 0.f;
    #pragma unroll
    for (int h = 0; h < HEADS; h++) r += g_acc[h] / g_acc[HEADS + h];
    out[0] = r + bias[0];
    #pragma unroll
    for (int t = 0; t < 8; t++) g_acc[t] = 0.f;    // reset for next replay
}

// ---------------------------------------------------------------------------
extern "C" void kernel_launch(void* const* d_in, const int* in_sizes, int n_in,
                              void* d_out, int out_size) {
    const float* node_feats = (const float*)d_in[0];
    const float* W_int   = (const float*)d_in[1];
    const float* asrc_i  = (const float*)d_in[2];
    const float* adst_i  = (const float*)d_in[3];
    const float* W_nh    = (const float*)d_in[4];
    const float* asrc_n  = (const float*)d_in[5];
    const float* adst_n  = (const float*)d_in[6];
    const float* att_w   = (const float*)d_in[7];
    const float* dense_w = (const float*)d_in[8];
    const float* dense_b = (const float*)d_in[9];
    const void*  edge_i  = d_in[10];
    const void*  edge_n  = d_in[11];
    float* out = (float*)d_out;

    detect_kernel<<<1, 32>>>(edge_i, edge_n);
    fill_kernel<<<((E_INT + E_NH) / 2 + 255) / 256, 256>>>(edge_i, edge_n);
    node_kernel<<<(NN + 255) / 256, 256>>>(node_feats, W_int, asrc_i, adst_i,
                                           W_nh, asrc_n, adst_n);
    consume_kernel<<<(2 * NN * 8 + 255) / 256, 256>>>();
    pool_kernel<<<(NN + 255) / 256, 256>>>(att_w, dense_w);
    finalize_kernel<<<1, 1>>>(dense_b, out);
}